// round 13
// baseline (speedup 1.0000x reference)
#include <cuda_runtime.h>
#include <cuda_bf16.h>
#include <cuda_fp16.h>
#include <cstdint>

#define N_NODES 50000
#define E_EDGES 800000
#define DIM 128
#define GROWS 64
#define NTILES ((N_NODES + GROWS - 1) / GROWS)
#define LDA 136        // padded A row length (bf16) -> conflict-free ldmatrix
#define CAP 128        // padded-CSR capacity per destination

// ---------------- device scratch (no allocations allowed) ----------------
__device__ __half g_xl[(size_t)N_NODES * DIM];
__device__ float  g_xr[(size_t)N_NODES * DIM];
__device__ int    g_cnt[N_NODES];
__device__ int    g_srcp[(size_t)N_NODES * CAP];
// B fragments merged: [ks][ng][lane] -> uint4 {hi.k01, hi.k89, lo.k01, lo.k89}
__device__ __align__(16) uint4 g_Bf[8192];

// ---------------- padded-CSR build ----------------
__global__ void zero_kernel() {
    int i = blockIdx.x * blockDim.x + threadIdx.x;
    if (i < N_NODES) g_cnt[i] = 0;
}
__global__ void fill_kernel(const int* __restrict__ ei) {
    int e = blockIdx.x * blockDim.x + threadIdx.x;
    if (e < E_EDGES) {
        int s = ei[e];
        int d = ei[E_EDGES + e];
        int p = atomicAdd(&g_cnt[d], 1);
        if (p < CAP) g_srcp[(size_t)d * CAP + p] = s;
    }
}

// ---------------- one-time W split into merged B fragments ----------------
__device__ __forceinline__ uint32_t pack_bf16(float a, float b) {
    __nv_bfloat16 ba = __float2bfloat16(a), bb = __float2bfloat16(b);
    return (uint32_t)__bfloat16_as_ushort(bb) << 16 | __bfloat16_as_ushort(ba);
}
__global__ void prep_b_kernel(const float* __restrict__ Wl, const float* __restrict__ Wr) {
    int i = blockIdx.x * blockDim.x + threadIdx.x;   // 0..8191
    if (i >= 8192) return;
    const int lane = i & 31;
    const int ng   = (i >> 5) & 31;
    const int ks   = i >> 10;
    const int n    = ng * 8 + (lane >> 2);
    const int k0   = ks * 16 + (lane & 3) * 2;
    const float* W = (n < 128) ? Wl : Wr;
    const int nn   = n & 127;
    const float v0 = W[(k0    ) * 128 + nn];
    const float v1 = W[(k0 + 1) * 128 + nn];
    const float v8 = W[(k0 + 8) * 128 + nn];
    const float v9 = W[(k0 + 9) * 128 + nn];
    float h0 = __bfloat162float(__float2bfloat16(v0));
    float h1 = __bfloat162float(__float2bfloat16(v1));
    float h8 = __bfloat162float(__float2bfloat16(v8));
    float h9 = __bfloat162float(__float2bfloat16(v9));
    g_Bf[i] = make_uint4(pack_bf16(h0, h1), pack_bf16(h8, h9),
                         pack_bf16(v0 - h0, v1 - h1), pack_bf16(v8 - h8, v9 - h9));
}

// ---------------- mma helpers ----------------
__device__ __forceinline__ uint32_t smem_u32(const void* p) {
    uint32_t a;
    asm("{ .reg .u64 t; cvta.to.shared.u64 t, %1; cvt.u32.u64 %0, t; }" : "=r"(a) : "l"(p));
    return a;
}
__device__ __forceinline__ void ldsm_x4(uint32_t* r, uint32_t addr) {
    asm volatile("ldmatrix.sync.aligned.m8n8.x4.shared.b16 {%0,%1,%2,%3}, [%4];"
                 : "=r"(r[0]), "=r"(r[1]), "=r"(r[2]), "=r"(r[3]) : "r"(addr));
}
__device__ __forceinline__ void mma_bf16(float* d, const uint32_t* a, uint32_t b0, uint32_t b1) {
    asm volatile(
        "mma.sync.aligned.m16n8k16.row.col.f32.bf16.bf16.f32 "
        "{%0,%1,%2,%3}, {%4,%5,%6,%7}, {%8,%9}, {%0,%1,%2,%3};"
        : "+f"(d[0]), "+f"(d[1]), "+f"(d[2]), "+f"(d[3])
        : "r"(a[0]), "r"(a[1]), "r"(a[2]), "r"(a[3]), "r"(b0), "r"(b1));
}

#define SM_BYTES 18432

// ---------------- LayerNorm + dual GEMM (tile 64 x 256, 2-pass split) ----------------
__global__ __launch_bounds__(512, 2)
void ln_gemm_kernel(const float* __restrict__ x,
                    const float* __restrict__ ln_g, const float* __restrict__ ln_b,
                    const float* __restrict__ bl, const float* __restrict__ br)
{
    __shared__ __align__(16) char smem[SM_BYTES];
    const uint32_t sb = smem_u32(smem);
    const int tid  = threadIdx.x;
    const int wid  = tid >> 5;
    const int lane = tid & 31;
    const int base = blockIdx.x * GROWS;

    // LayerNorm -> bf16 A image (16 warps x 4 rows)
    {
        const float4 gv = reinterpret_cast<const float4*>(ln_g)[lane];
        const float4 bv = reinterpret_cast<const float4*>(ln_b)[lane];
        #pragma unroll
        for (int i = 0; i < 4; i++) {
            const int nl = i * 16 + wid;
            const int n  = base + nl;
            float4 v = make_float4(0.f, 0.f, 0.f, 0.f);
            if (n < N_NODES)
                v = reinterpret_cast<const float4*>(x + (size_t)n * DIM)[lane];
            float s = v.x + v.y + v.z + v.w;
            #pragma unroll
            for (int w = 16; w; w >>= 1) s += __shfl_xor_sync(0xffffffffu, s, w);
            const float mu = s * (1.0f / 128.0f);
            const float dx = v.x - mu, dy = v.y - mu, dz = v.z - mu, dw = v.w - mu;
            float q = dx * dx + dy * dy + dz * dz + dw * dw;
            #pragma unroll
            for (int w = 16; w; w >>= 1) q += __shfl_xor_sync(0xffffffffu, q, w);
            const float rs = rsqrtf(q * (1.0f / 128.0f) + 1e-5f);
            const uint32_t off = (uint32_t)(nl * LDA + lane * 4) * 2;
            *reinterpret_cast<uint2*>(smem + off) = make_uint2(
                pack_bf16(dx * rs * gv.x + bv.x, dy * rs * gv.y + bv.y),
                pack_bf16(dz * rs * gv.z + bv.z, dw * rs * gv.w + bv.w));
        }
    }
    __syncthreads();

    // ---- MMA mainloop: warp tile 32x32, 2 passes, merged B fragments ----
    const int wm = wid & 1;
    const int wn = wid >> 1;

    const uint32_t aRow = (uint32_t)(wm * 32 + (lane & 15));
    const uint32_t aK   = (uint32_t)((lane >> 4) * 8);
    const uint32_t aHi  = sb + (aRow * LDA + aK) * 2;

    float d[2][4][4];
    #pragma unroll
    for (int mf = 0; mf < 2; mf++)
        #pragma unroll
        for (int nf = 0; nf < 4; nf++)
            #pragma unroll
            for (int j = 0; j < 4; j++) d[mf][nf][j] = 0.f;

    #pragma unroll 1
    for (int ks = 0; ks < 8; ks++) {
        const uint32_t kb = (uint32_t)ks * 32;
        uint32_t ah[2][4];
        ldsm_x4(ah[0], aHi + kb);
        ldsm_x4(ah[1], aHi + 16 * LDA * 2 + kb);
        const int fbase = (ks * 32 + wn * 4) * 32 + lane;
        uint4 bf[4];
        #pragma unroll
        for (int nf = 0; nf < 4; nf++) bf[nf] = g_Bf[fbase + nf * 32];
        #pragma unroll
        for (int nf = 0; nf < 4; nf++)
            #pragma unroll
            for (int mf = 0; mf < 2; mf++) {
                mma_bf16(d[mf][nf], ah[mf], bf[nf].x, bf[nf].y);
                mma_bf16(d[mf][nf], ah[mf], bf[nf].z, bf[nf].w);
            }
    }

    // ---- Epilogue: smem-staged, coalesced stores ----
    const int half  = wn >> 2;
    const int cbase = (wn & 3) * 32;
    __syncthreads();

    // Phase A: xl (fp16)
    if (half == 0) {
        #pragma unroll
        for (int mf = 0; mf < 2; mf++) {
            const int r0 = wm * 32 + mf * 16 + (lane >> 2);
            #pragma unroll
            for (int nf = 0; nf < 4; nf++) {
                const int c = cbase + nf * 8 + (lane & 3) * 2;
                const float2 bv = *reinterpret_cast<const float2*>(&bl[c]);
                *reinterpret_cast<__half2*>(smem + (r0 * 136 + c) * 2) =
                    __floats2half2_rn(d[mf][nf][0] + bv.x, d[mf][nf][1] + bv.y);
                *reinterpret_cast<__half2*>(smem + ((r0 + 8) * 136 + c) * 2) =
                    __floats2half2_rn(d[mf][nf][2] + bv.x, d[mf][nf][3] + bv.y);
            }
        }
    }
    __syncthreads();
    #pragma unroll
    for (int i = tid; i < 1024; i += 512) {
        const int row = i >> 4, c16 = i & 15;
        const int n = base + row;
        if (n < N_NODES)
            *reinterpret_cast<uint4*>(reinterpret_cast<char*>(g_xl) + ((size_t)n * DIM + c16 * 8) * 2) =
                *reinterpret_cast<const uint4*>(smem + row * 272 + c16 * 16);
    }

    // Phases B/C: xr (fp32) in two 64-col half-tiles
    #pragma unroll 1
    for (int ph = 0; ph < 2; ph++) {
        __syncthreads();
        if (half == 1 && ((wn >> 1) & 1) == ph) {
            const int cl0 = (wn & 1) * 32;
            #pragma unroll
            for (int mf = 0; mf < 2; mf++) {
                const int r0 = wm * 32 + mf * 16 + (lane >> 2);
                #pragma unroll
                for (int nf = 0; nf < 4; nf++) {
                    const int cl = cl0 + nf * 8 + (lane & 3) * 2;
                    const float2 bv = *reinterpret_cast<const float2*>(&br[ph * 64 + cl]);
                    *reinterpret_cast<float2*>(smem + (r0 * 72 + cl) * 4) =
                        make_float2(d[mf][nf][0] + bv.x, d[mf][nf][1] + bv.y);
                    *reinterpret_cast<float2*>(smem + ((r0 + 8) * 72 + cl) * 4) =
                        make_float2(d[mf][nf][2] + bv.x, d[mf][nf][3] + bv.y);
                }
            }
        }
        __syncthreads();
        #pragma unroll
        for (int i = tid; i < 1024; i += 512) {
            const int row = i >> 4, c16 = i & 15;
            const int n = base + row;
            if (n < N_NODES)
                *reinterpret_cast<uint4*>(g_xr + (size_t)n * DIM + ph * 64 + c16 * 4) =
                    *reinterpret_cast<const uint4*>(smem + row * 288 + c16 * 16);
        }
    }
}

// ---------------- aggregation: 2 warps per destination node ----------------
// Block = 256 threads = 8 warps = 4 nodes (12500 * 4 == 50000 exactly -> no
// early exits before the barrier). Warp pair splits the edge list in half;
// partial (dsum, acc) are plain sums (direct exp, no max) -> combine via smem.
__global__ __launch_bounds__(256)
void agg_kernel(const float* __restrict__ x, const float* __restrict__ att,
                const float* __restrict__ bias, float* __restrict__ out)
{
    __shared__ float4 s_acc[8][32];
    __shared__ float  s_d[8][32];

    const int warp = threadIdx.x >> 5;
    const int lane = threadIdx.x & 31;
    const int pair = warp >> 1;          // node slot within block
    const int sub  = warp & 1;           // which half of the edge list
    const int nid  = blockIdx.x * 4 + pair;

    const int deg = min(g_cnt[nid], CAP);
    const size_t st = (size_t)nid * CAP;
    const int half_deg = (deg + 1) >> 1;
    const int lo = sub * half_deg;
    const int hi = min(deg, lo + half_deg);

    const float4 xr4 = *reinterpret_cast<const float4*>(g_xr + (size_t)nid * DIM + lane * 4);
    const float4 a4  = reinterpret_cast<const float4*>(att)[lane];
    const float4 aP  = make_float4(0.575f * a4.x, 0.575f * a4.y, 0.575f * a4.z, 0.575f * a4.w);
    const float4 aQ  = make_float4(0.425f * a4.x, 0.425f * a4.y, 0.425f * a4.z, 0.425f * a4.w);

    float  dsum = 0.f;
    float4 acc  = make_float4(0.f, 0.f, 0.f, 0.f);

    const __half* xlp = g_xl;

    for (int b = lo; b < hi; b += 32) {
        const int cnt = min(32, hi - b);
        const int my_src = (lane < cnt) ? g_srcp[st + b + lane] : 0;

        int e = 0;
        for (; e + 4 <= cnt; e += 4) {
            const int s0 = __shfl_sync(0xffffffffu, my_src, e);
            const int s1 = __shfl_sync(0xffffffffu, my_src, e + 1);
            const int s2 = __shfl_sync(0xffffffffu, my_src, e + 2);
            const int s3 = __shfl_sync(0xffffffffu, my_src, e + 3);
            const uint2 u0 = *reinterpret_cast<const uint2*>(xlp + (size_t)s0 * DIM + lane * 4);
            const uint2 u1 = *reinterpret_cast<const uint2*>(xlp + (size_t)s1 * DIM + lane * 4);
            const uint2 u2 = *reinterpret_cast<const uint2*>(xlp + (size_t)s2 * DIM + lane * 4);
            const uint2 u3 = *reinterpret_cast<const uint2*>(xlp + (size_t)s3 * DIM + lane * 4);

            const float2 f0a = __half22float2(*reinterpret_cast<const __half2*>(&u0.x));
            const float2 f0b = __half22float2(*reinterpret_cast<const __half2*>(&u0.y));
            const float2 f1a = __half22float2(*reinterpret_cast<const __half2*>(&u1.x));
            const float2 f1b = __half22float2(*reinterpret_cast<const __half2*>(&u1.y));
            const float2 f2a = __half22float2(*reinterpret_cast<const __half2*>(&u2.x));
            const float2 f2b = __half22float2(*reinterpret_cast<const __half2*>(&u2.y));
            const float2 f3a = __half22float2(*reinterpret_cast<const __half2*>(&u3.x));
            const float2 f3b = __half22float2(*reinterpret_cast<const __half2*>(&u3.y));

            float p0, p1, p2, p3, z;
            z = f0a.x + xr4.x; p0  = aP.x * z + aQ.x * fabsf(z);
            z = f0a.y + xr4.y; p0 += aP.y * z + aQ.y * fabsf(z);
            z = f0b.x + xr4.z; p0 += aP.z * z + aQ.z * fabsf(z);
            z = f0b.y + xr4.w; p0 += aP.w * z + aQ.w * fabsf(z);
            z = f1a.x + xr4.x; p1  = aP.x * z + aQ.x * fabsf(z);
            z = f1a.y + xr4.y; p1 += aP.y * z + aQ.y * fabsf(z);
            z = f1b.x + xr4.z; p1 += aP.z * z + aQ.z * fabsf(z);
            z = f1b.y + xr4.w; p1 += aP.w * z + aQ.w * fabsf(z);
            z = f2a.x + xr4.x; p2  = aP.x * z + aQ.x * fabsf(z);
            z = f2a.y + xr4.y; p2 += aP.y * z + aQ.y * fabsf(z);
            z = f2b.x + xr4.z; p2 += aP.z * z + aQ.z * fabsf(z);
            z = f2b.y + xr4.w; p2 += aP.w * z + aQ.w * fabsf(z);
            z = f3a.x + xr4.x; p3  = aP.x * z + aQ.x * fabsf(z);
            z = f3a.y + xr4.y; p3 += aP.y * z + aQ.y * fabsf(z);
            z = f3b.x + xr4.z; p3 += aP.z * z + aQ.z * fabsf(z);
            z = f3b.y + xr4.w; p3 += aP.w * z + aQ.w * fabsf(z);

            p0 += __shfl_xor_sync(0xffffffffu, p0, 1);
            p1 += __shfl_xor_sync(0xffffffffu, p1, 1);
            p2 += __shfl_xor_sync(0xffffffffu, p2, 1);
            p3 += __shfl_xor_sync(0xffffffffu, p3, 1);
            p0 += __shfl_xor_sync(0xffffffffu, p0, 2);
            p1 += __shfl_xor_sync(0xffffffffu, p1, 2);
            p2 += __shfl_xor_sync(0xffffffffu, p2, 2);
            p3 += __shfl_xor_sync(0xffffffffu, p3, 2);

            const float w0 = __expf(p0);
            const float w1 = __expf(p1);
            const float w2 = __expf(p2);
            const float w3 = __expf(p3);
            dsum += (w0 + w1) + (w2 + w3);
            acc.x = fmaf(f3a.x, w3, fmaf(f2a.x, w2, fmaf(f1a.x, w1, fmaf(f0a.x, w0, acc.x))));
            acc.y = fmaf(f3a.y, w3, fmaf(f2a.y, w2, fmaf(f1a.y, w1, fmaf(f0a.y, w0, acc.y))));
            acc.z = fmaf(f3b.x, w3, fmaf(f2b.x, w2, fmaf(f1b.x, w1, fmaf(f0b.x, w0, acc.z))));
            acc.w = fmaf(f3b.y, w3, fmaf(f2b.y, w2, fmaf(f1b.y, w1, fmaf(f0b.y, w0, acc.w))));
        }
        for (; e < cnt; e++) {
            const int s0 = __shfl_sync(0xffffffffu, my_src, e);
            const uint2 u0 = *reinterpret_cast<const uint2*>(xlp + (size_t)s0 * DIM + lane * 4);
            const float2 f0a = __half22float2(*reinterpret_cast<const __half2*>(&u0.x));
            const float2 f0b = __half22float2(*reinterpret_cast<const __half2*>(&u0.y));
            float p0, z;
            z = f0a.x + xr4.x; p0  = aP.x * z + aQ.x * fabsf(z);
            z = f0a.y + xr4.y; p0 += aP.y * z + aQ.y * fabsf(z);
            z = f0b.x + xr4.z; p0 += aP.z * z + aQ.z * fabsf(z);
            z = f0b.y + xr4.w; p0 += aP.w * z + aQ.w * fabsf(z);
            p0 += __shfl_xor_sync(0xffffffffu, p0, 1);
            p0 += __shfl_xor_sync(0xffffffffu, p0, 2);
            const float w0 = __expf(p0);
            dsum += w0;
            acc.x = fmaf(f0a.x, w0, acc.x);
            acc.y = fmaf(f0a.y, w0, acc.y);
            acc.z = fmaf(f0b.x, w0, acc.z);
            acc.w = fmaf(f0b.y, w0, acc.w);
        }
    }

    // Combine the two warps' partials via smem
    s_acc[warp][lane] = acc;
    s_d[warp][lane]   = dsum;
    __syncthreads();

    if (sub == 0) {
        const float4 o2 = s_acc[warp + 1][lane];
        acc.x += o2.x; acc.y += o2.y; acc.z += o2.z; acc.w += o2.w;
        dsum  += s_d[warp + 1][lane];

        const float inv = 1.0f / (dsum + 1e-16f);
        const float4 bias4 = reinterpret_cast<const float4*>(bias)[lane];
        const float4 x4 = *reinterpret_cast<const float4*>(x + (size_t)nid * DIM + lane * 4);
        float4 o;
        o.x = x4.x + fmaxf(fmaf(acc.x, inv, bias4.x), 0.f);
        o.y = x4.y + fmaxf(fmaf(acc.y, inv, bias4.y), 0.f);
        o.z = x4.z + fmaxf(fmaf(acc.z, inv, bias4.z), 0.f);
        o.w = x4.w + fmaxf(fmaf(acc.w, inv, bias4.w), 0.f);
        *reinterpret_cast<float4*>(out + (size_t)nid * DIM + lane * 4) = o;
    }
}

// ---------------- launch ----------------
extern "C" void kernel_launch(void* const* d_in, const int* in_sizes, int n_in,
                              void* d_out, int out_size)
{
    const float* x    = (const float*)d_in[0];
    const int*   ei   = (const int*)d_in[1];
    const float* lng  = (const float*)d_in[2];
    const float* lnb  = (const float*)d_in[3];
    const float* Wl   = (const float*)d_in[4];
    const float* bl   = (const float*)d_in[5];
    const float* Wr   = (const float*)d_in[6];
    const float* br   = (const float*)d_in[7];
    const float* att  = (const float*)d_in[8];
    const float* bias = (const float*)d_in[9];
    float* out = (float*)d_out;

    static cudaStream_t s_csr = nullptr;
    static cudaEvent_t  ev_fork = nullptr, ev_join = nullptr;
    if (!s_csr) {
        cudaStreamCreateWithFlags(&s_csr, cudaStreamNonBlocking);
        cudaEventCreateWithFlags(&ev_fork, cudaEventDisableTiming);
        cudaEventCreateWithFlags(&ev_join, cudaEventDisableTiming);
    }

    // fork: padded-CSR build on side stream
    cudaEventRecord(ev_fork, 0);
    cudaStreamWaitEvent(s_csr, ev_fork, 0);
    zero_kernel<<<(N_NODES + 255) / 256, 256, 0, s_csr>>>();
    fill_kernel<<<(E_EDGES + 255) / 256, 256, 0, s_csr>>>(ei);
    cudaEventRecord(ev_join, s_csr);

    // main stream: W fragment split + LN + mma GEMM
    prep_b_kernel<<<32, 256>>>(Wl, Wr);
    ln_gemm_kernel<<<NTILES, 512>>>(x, lng, lnb, bl, br);

    // join, then aggregate (4 nodes per 256-thread block; 12500*4 == 50000)
    cudaStreamWaitEvent(0, ev_join, 0);
    agg_kernel<<<N_NODES / 4, 256>>>(x, att, bias, out);
}

// round 14
// speedup vs baseline: 1.0926x; 1.0926x over previous
#include <cuda_runtime.h>
#include <cuda_bf16.h>
#include <cuda_fp16.h>
#include <cstdint>

#define N_NODES 50000
#define E_EDGES 800000
#define DIM 128
#define GROWS 64
#define NTILES ((N_NODES + GROWS - 1) / GROWS)
#define LDA 136        // padded A row length (bf16) -> conflict-free ldmatrix
#define CAP 128        // padded-CSR capacity per destination

// ---------------- device scratch (no allocations allowed) ----------------
__device__ __half g_xl[(size_t)N_NODES * DIM];
__device__ float  g_xr[(size_t)N_NODES * DIM];
__device__ int    g_cnt[N_NODES];
__device__ int    g_srcp[(size_t)N_NODES * CAP];
// B fragments merged: [ks][ng][lane] -> uint4 {hi.k01, hi.k89, lo.k01, lo.k89}
__device__ __align__(16) uint4 g_Bf[8192];

// ---------------- padded-CSR build ----------------
__global__ void zero_kernel() {
    int i = blockIdx.x * blockDim.x + threadIdx.x;
    if (i < N_NODES) g_cnt[i] = 0;
}
__global__ void fill_kernel(const int* __restrict__ ei) {
    int e = blockIdx.x * blockDim.x + threadIdx.x;
    if (e < E_EDGES) {
        int s = ei[e];
        int d = ei[E_EDGES + e];
        int p = atomicAdd(&g_cnt[d], 1);
        if (p < CAP) g_srcp[(size_t)d * CAP + p] = s;
    }
}

// ---------------- one-time W split into merged B fragments ----------------
__device__ __forceinline__ uint32_t pack_bf16(float a, float b) {
    __nv_bfloat16 ba = __float2bfloat16(a), bb = __float2bfloat16(b);
    return (uint32_t)__bfloat16_as_ushort(bb) << 16 | __bfloat16_as_ushort(ba);
}
__global__ void prep_b_kernel(const float* __restrict__ Wl, const float* __restrict__ Wr) {
    int i = blockIdx.x * blockDim.x + threadIdx.x;   // 0..8191
    if (i >= 8192) return;
    const int lane = i & 31;
    const int ng   = (i >> 5) & 31;
    const int ks   = i >> 10;
    const int n    = ng * 8 + (lane >> 2);
    const int k0   = ks * 16 + (lane & 3) * 2;
    const float* W = (n < 128) ? Wl : Wr;
    const int nn   = n & 127;
    const float v0 = W[(k0    ) * 128 + nn];
    const float v1 = W[(k0 + 1) * 128 + nn];
    const float v8 = W[(k0 + 8) * 128 + nn];
    const float v9 = W[(k0 + 9) * 128 + nn];
    float h0 = __bfloat162float(__float2bfloat16(v0));
    float h1 = __bfloat162float(__float2bfloat16(v1));
    float h8 = __bfloat162float(__float2bfloat16(v8));
    float h9 = __bfloat162float(__float2bfloat16(v9));
    g_Bf[i] = make_uint4(pack_bf16(h0, h1), pack_bf16(h8, h9),
                         pack_bf16(v0 - h0, v1 - h1), pack_bf16(v8 - h8, v9 - h9));
}

// ---------------- mma helpers ----------------
__device__ __forceinline__ uint32_t smem_u32(const void* p) {
    uint32_t a;
    asm("{ .reg .u64 t; cvta.to.shared.u64 t, %1; cvt.u32.u64 %0, t; }" : "=r"(a) : "l"(p));
    return a;
}
__device__ __forceinline__ void ldsm_x4(uint32_t* r, uint32_t addr) {
    asm volatile("ldmatrix.sync.aligned.m8n8.x4.shared.b16 {%0,%1,%2,%3}, [%4];"
                 : "=r"(r[0]), "=r"(r[1]), "=r"(r[2]), "=r"(r[3]) : "r"(addr));
}
__device__ __forceinline__ void mma_bf16(float* d, const uint32_t* a, uint32_t b0, uint32_t b1) {
    asm volatile(
        "mma.sync.aligned.m16n8k16.row.col.f32.bf16.bf16.f32 "
        "{%0,%1,%2,%3}, {%4,%5,%6,%7}, {%8,%9}, {%0,%1,%2,%3};"
        : "+f"(d[0]), "+f"(d[1]), "+f"(d[2]), "+f"(d[3])
        : "r"(a[0]), "r"(a[1]), "r"(a[2]), "r"(a[3]), "r"(b0), "r"(b1));
}

#define SM_BYTES 18432

// ---------------- LayerNorm + dual GEMM (tile 64 x 256, 2-pass split) ----------------
__global__ __launch_bounds__(512, 2)
void ln_gemm_kernel(const float* __restrict__ x,
                    const float* __restrict__ ln_g, const float* __restrict__ ln_b,
                    const float* __restrict__ bl, const float* __restrict__ br)
{
    __shared__ __align__(16) char smem[SM_BYTES];
    const uint32_t sb = smem_u32(smem);
    const int tid  = threadIdx.x;
    const int wid  = tid >> 5;
    const int lane = tid & 31;
    const int base = blockIdx.x * GROWS;

    // LayerNorm -> bf16 A image (16 warps x 4 rows)
    {
        const float4 gv = reinterpret_cast<const float4*>(ln_g)[lane];
        const float4 bv = reinterpret_cast<const float4*>(ln_b)[lane];
        #pragma unroll
        for (int i = 0; i < 4; i++) {
            const int nl = i * 16 + wid;
            const int n  = base + nl;
            float4 v = make_float4(0.f, 0.f, 0.f, 0.f);
            if (n < N_NODES)
                v = reinterpret_cast<const float4*>(x + (size_t)n * DIM)[lane];
            float s = v.x + v.y + v.z + v.w;
            #pragma unroll
            for (int w = 16; w; w >>= 1) s += __shfl_xor_sync(0xffffffffu, s, w);
            const float mu = s * (1.0f / 128.0f);
            const float dx = v.x - mu, dy = v.y - mu, dz = v.z - mu, dw = v.w - mu;
            float q = dx * dx + dy * dy + dz * dz + dw * dw;
            #pragma unroll
            for (int w = 16; w; w >>= 1) q += __shfl_xor_sync(0xffffffffu, q, w);
            const float rs = rsqrtf(q * (1.0f / 128.0f) + 1e-5f);
            const uint32_t off = (uint32_t)(nl * LDA + lane * 4) * 2;
            *reinterpret_cast<uint2*>(smem + off) = make_uint2(
                pack_bf16(dx * rs * gv.x + bv.x, dy * rs * gv.y + bv.y),
                pack_bf16(dz * rs * gv.z + bv.z, dw * rs * gv.w + bv.w));
        }
    }
    __syncthreads();

    // ---- MMA mainloop: warp tile 32x32, 2 passes, merged B fragments ----
    const int wm = wid & 1;
    const int wn = wid >> 1;

    const uint32_t aRow = (uint32_t)(wm * 32 + (lane & 15));
    const uint32_t aK   = (uint32_t)((lane >> 4) * 8);
    const uint32_t aHi  = sb + (aRow * LDA + aK) * 2;

    float d[2][4][4];
    #pragma unroll
    for (int mf = 0; mf < 2; mf++)
        #pragma unroll
        for (int nf = 0; nf < 4; nf++)
            #pragma unroll
            for (int j = 0; j < 4; j++) d[mf][nf][j] = 0.f;

    #pragma unroll 1
    for (int ks = 0; ks < 8; ks++) {
        const uint32_t kb = (uint32_t)ks * 32;
        uint32_t ah[2][4];
        ldsm_x4(ah[0], aHi + kb);
        ldsm_x4(ah[1], aHi + 16 * LDA * 2 + kb);
        const int fbase = (ks * 32 + wn * 4) * 32 + lane;
        uint4 bf[4];
        #pragma unroll
        for (int nf = 0; nf < 4; nf++) bf[nf] = g_Bf[fbase + nf * 32];
        #pragma unroll
        for (int nf = 0; nf < 4; nf++)
            #pragma unroll
            for (int mf = 0; mf < 2; mf++) {
                mma_bf16(d[mf][nf], ah[mf], bf[nf].x, bf[nf].y);
                mma_bf16(d[mf][nf], ah[mf], bf[nf].z, bf[nf].w);
            }
    }

    // ---- Epilogue: smem-staged, coalesced stores ----
    const int half  = wn >> 2;
    const int cbase = (wn & 3) * 32;
    __syncthreads();

    // Phase A: xl (fp16)
    if (half == 0) {
        #pragma unroll
        for (int mf = 0; mf < 2; mf++) {
            const int r0 = wm * 32 + mf * 16 + (lane >> 2);
            #pragma unroll
            for (int nf = 0; nf < 4; nf++) {
                const int c = cbase + nf * 8 + (lane & 3) * 2;
                const float2 bv = *reinterpret_cast<const float2*>(&bl[c]);
                *reinterpret_cast<__half2*>(smem + (r0 * 136 + c) * 2) =
                    __floats2half2_rn(d[mf][nf][0] + bv.x, d[mf][nf][1] + bv.y);
                *reinterpret_cast<__half2*>(smem + ((r0 + 8) * 136 + c) * 2) =
                    __floats2half2_rn(d[mf][nf][2] + bv.x, d[mf][nf][3] + bv.y);
            }
        }
    }
    __syncthreads();
    #pragma unroll
    for (int i = tid; i < 1024; i += 512) {
        const int row = i >> 4, c16 = i & 15;
        const int n = base + row;
        if (n < N_NODES)
            *reinterpret_cast<uint4*>(reinterpret_cast<char*>(g_xl) + ((size_t)n * DIM + c16 * 8) * 2) =
                *reinterpret_cast<const uint4*>(smem + row * 272 + c16 * 16);
    }

    // Phases B/C: xr (fp32) in two 64-col half-tiles
    #pragma unroll 1
    for (int ph = 0; ph < 2; ph++) {
        __syncthreads();
        if (half == 1 && ((wn >> 1) & 1) == ph) {
            const int cl0 = (wn & 1) * 32;
            #pragma unroll
            for (int mf = 0; mf < 2; mf++) {
                const int r0 = wm * 32 + mf * 16 + (lane >> 2);
                #pragma unroll
                for (int nf = 0; nf < 4; nf++) {
                    const int cl = cl0 + nf * 8 + (lane & 3) * 2;
                    const float2 bv = *reinterpret_cast<const float2*>(&br[ph * 64 + cl]);
                    *reinterpret_cast<float2*>(smem + (r0 * 72 + cl) * 4) =
                        make_float2(d[mf][nf][0] + bv.x, d[mf][nf][1] + bv.y);
                    *reinterpret_cast<float2*>(smem + ((r0 + 8) * 72 + cl) * 4) =
                        make_float2(d[mf][nf][2] + bv.x, d[mf][nf][3] + bv.y);
                }
            }
        }
        __syncthreads();
        #pragma unroll
        for (int i = tid; i < 1024; i += 512) {
            const int row = i >> 4, c16 = i & 15;
            const int n = base + row;
            if (n < N_NODES)
                *reinterpret_cast<uint4*>(g_xr + (size_t)n * DIM + ph * 64 + c16 * 4) =
                    *reinterpret_cast<const uint4*>(smem + row * 288 + c16 * 16);
        }
    }
}

// ---------------- warp-per-destination aggregation, software-pipelined gather ----------------
// One warp per node (R12 structure). 4-edge groups; group g+1's scattered loads
// are issued BEFORE group g's compute -> memory latency exposed once per chunk,
// not once per group.
__global__ __launch_bounds__(256)
void agg_kernel(const float* __restrict__ x, const float* __restrict__ att,
                const float* __restrict__ bias, float* __restrict__ out)
{
    const int warp = threadIdx.x >> 5;
    const int lane = threadIdx.x & 31;
    const int nid  = blockIdx.x * 8 + warp;
    if (nid >= N_NODES) return;

    const int deg = min(g_cnt[nid], CAP);
    const size_t st = (size_t)nid * CAP;

    const float4 xr4 = *reinterpret_cast<const float4*>(g_xr + (size_t)nid * DIM + lane * 4);
    const float4 a4  = reinterpret_cast<const float4*>(att)[lane];
    const float4 aP  = make_float4(0.575f * a4.x, 0.575f * a4.y, 0.575f * a4.z, 0.575f * a4.w);
    const float4 aQ  = make_float4(0.425f * a4.x, 0.425f * a4.y, 0.425f * a4.z, 0.425f * a4.w);

    float  dsum = 0.f;
    float4 acc  = make_float4(0.f, 0.f, 0.f, 0.f);

    const __half* xlp = g_xl;

    for (int b = 0; b < deg; b += 32) {
        const int cnt = min(32, deg - b);
        const int my_src = (lane < cnt) ? g_srcp[st + b + lane] : 0;
        const int G = cnt >> 2;               // number of full 4-edge groups

        uint2 u0, u1, u2, u3;                 // current group's data
        if (G > 0) {
            const int s0 = __shfl_sync(0xffffffffu, my_src, 0);
            const int s1 = __shfl_sync(0xffffffffu, my_src, 1);
            const int s2 = __shfl_sync(0xffffffffu, my_src, 2);
            const int s3 = __shfl_sync(0xffffffffu, my_src, 3);
            u0 = *reinterpret_cast<const uint2*>(xlp + (size_t)s0 * DIM + lane * 4);
            u1 = *reinterpret_cast<const uint2*>(xlp + (size_t)s1 * DIM + lane * 4);
            u2 = *reinterpret_cast<const uint2*>(xlp + (size_t)s2 * DIM + lane * 4);
            u3 = *reinterpret_cast<const uint2*>(xlp + (size_t)s3 * DIM + lane * 4);
        }

        for (int g = 0; g < G; g++) {
            // prefetch next group before computing current
            uint2 v0, v1, v2, v3;
            if (g + 1 < G) {
                const int e = (g + 1) * 4;
                const int s0 = __shfl_sync(0xffffffffu, my_src, e);
                const int s1 = __shfl_sync(0xffffffffu, my_src, e + 1);
                const int s2 = __shfl_sync(0xffffffffu, my_src, e + 2);
                const int s3 = __shfl_sync(0xffffffffu, my_src, e + 3);
                v0 = *reinterpret_cast<const uint2*>(xlp + (size_t)s0 * DIM + lane * 4);
                v1 = *reinterpret_cast<const uint2*>(xlp + (size_t)s1 * DIM + lane * 4);
                v2 = *reinterpret_cast<const uint2*>(xlp + (size_t)s2 * DIM + lane * 4);
                v3 = *reinterpret_cast<const uint2*>(xlp + (size_t)s3 * DIM + lane * 4);
            }

            const float2 f0a = __half22float2(*reinterpret_cast<const __half2*>(&u0.x));
            const float2 f0b = __half22float2(*reinterpret_cast<const __half2*>(&u0.y));
            const float2 f1a = __half22float2(*reinterpret_cast<const __half2*>(&u1.x));
            const float2 f1b = __half22float2(*reinterpret_cast<const __half2*>(&u1.y));
            const float2 f2a = __half22float2(*reinterpret_cast<const __half2*>(&u2.x));
            const float2 f2b = __half22float2(*reinterpret_cast<const __half2*>(&u2.y));
            const float2 f3a = __half22float2(*reinterpret_cast<const __half2*>(&u3.x));
            const float2 f3b = __half22float2(*reinterpret_cast<const __half2*>(&u3.y));

            float p0, p1, p2, p3, z;
            z = f0a.x + xr4.x; p0  = aP.x * z + aQ.x * fabsf(z);
            z = f0a.y + xr4.y; p0 += aP.y * z + aQ.y * fabsf(z);
            z = f0b.x + xr4.z; p0 += aP.z * z + aQ.z * fabsf(z);
            z = f0b.y + xr4.w; p0 += aP.w * z + aQ.w * fabsf(z);
            z = f1a.x + xr4.x; p1  = aP.x * z + aQ.x * fabsf(z);
            z = f1a.y + xr4.y; p1 += aP.y * z + aQ.y * fabsf(z);
            z = f1b.x + xr4.z; p1 += aP.z * z + aQ.z * fabsf(z);
            z = f1b.y + xr4.w; p1 += aP.w * z + aQ.w * fabsf(z);
            z = f2a.x + xr4.x; p2  = aP.x * z + aQ.x * fabsf(z);
            z = f2a.y + xr4.y; p2 += aP.y * z + aQ.y * fabsf(z);
            z = f2b.x + xr4.z; p2 += aP.z * z + aQ.z * fabsf(z);
            z = f2b.y + xr4.w; p2 += aP.w * z + aQ.w * fabsf(z);
            z = f3a.x + xr4.x; p3  = aP.x * z + aQ.x * fabsf(z);
            z = f3a.y + xr4.y; p3 += aP.y * z + aQ.y * fabsf(z);
            z = f3b.x + xr4.z; p3 += aP.z * z + aQ.z * fabsf(z);
            z = f3b.y + xr4.w; p3 += aP.w * z + aQ.w * fabsf(z);

            p0 += __shfl_xor_sync(0xffffffffu, p0, 1);
            p1 += __shfl_xor_sync(0xffffffffu, p1, 1);
            p2 += __shfl_xor_sync(0xffffffffu, p2, 1);
            p3 += __shfl_xor_sync(0xffffffffu, p3, 1);
            p0 += __shfl_xor_sync(0xffffffffu, p0, 2);
            p1 += __shfl_xor_sync(0xffffffffu, p1, 2);
            p2 += __shfl_xor_sync(0xffffffffu, p2, 2);
            p3 += __shfl_xor_sync(0xffffffffu, p3, 2);

            const float w0 = __expf(p0);
            const float w1 = __expf(p1);
            const float w2 = __expf(p2);
            const float w3 = __expf(p3);
            dsum += (w0 + w1) + (w2 + w3);
            acc.x = fmaf(f3a.x, w3, fmaf(f2a.x, w2, fmaf(f1a.x, w1, fmaf(f0a.x, w0, acc.x))));
            acc.y = fmaf(f3a.y, w3, fmaf(f2a.y, w2, fmaf(f1a.y, w1, fmaf(f0a.y, w0, acc.y))));
            acc.z = fmaf(f3b.x, w3, fmaf(f2b.x, w2, fmaf(f1b.x, w1, fmaf(f0b.x, w0, acc.z))));
            acc.w = fmaf(f3b.y, w3, fmaf(f2b.y, w2, fmaf(f1b.y, w1, fmaf(f0b.y, w0, acc.w))));

            u0 = v0; u1 = v1; u2 = v2; u3 = v3;
        }

        // tail edges (cnt % 4)
        for (int e = G * 4; e < cnt; e++) {
            const int s0 = __shfl_sync(0xffffffffu, my_src, e);
            const uint2 t0 = *reinterpret_cast<const uint2*>(xlp + (size_t)s0 * DIM + lane * 4);
            const float2 f0a = __half22float2(*reinterpret_cast<const __half2*>(&t0.x));
            const float2 f0b = __half22float2(*reinterpret_cast<const __half2*>(&t0.y));
            float p0, z;
            z = f0a.x + xr4.x; p0  = aP.x * z + aQ.x * fabsf(z);
            z = f0a.y + xr4.y; p0 += aP.y * z + aQ.y * fabsf(z);
            z = f0b.x + xr4.z; p0 += aP.z * z + aQ.z * fabsf(z);
            z = f0b.y + xr4.w; p0 += aP.w * z + aQ.w * fabsf(z);
            p0 += __shfl_xor_sync(0xffffffffu, p0, 1);
            p0 += __shfl_xor_sync(0xffffffffu, p0, 2);
            const float w0 = __expf(p0);
            dsum += w0;
            acc.x = fmaf(f0a.x, w0, acc.x);
            acc.y = fmaf(f0a.y, w0, acc.y);
            acc.z = fmaf(f0b.x, w0, acc.z);
            acc.w = fmaf(f0b.y, w0, acc.w);
        }
    }

    const float inv = 1.0f / (dsum + 1e-16f);
    const float4 bias4 = reinterpret_cast<const float4*>(bias)[lane];
    const float4 x4 = *reinterpret_cast<const float4*>(x + (size_t)nid * DIM + lane * 4);
    float4 o;
    o.x = x4.x + fmaxf(fmaf(acc.x, inv, bias4.x), 0.f);
    o.y = x4.y + fmaxf(fmaf(acc.y, inv, bias4.y), 0.f);
    o.z = x4.z + fmaxf(fmaf(acc.z, inv, bias4.z), 0.f);
    o.w = x4.w + fmaxf(fmaf(acc.w, inv, bias4.w), 0.f);
    *reinterpret_cast<float4*>(out + (size_t)nid * DIM + lane * 4) = o;
}

// ---------------- launch ----------------
extern "C" void kernel_launch(void* const* d_in, const int* in_sizes, int n_in,
                              void* d_out, int out_size)
{
    const float* x    = (const float*)d_in[0];
    const int*   ei   = (const int*)d_in[1];
    const float* lng  = (const float*)d_in[2];
    const float* lnb  = (const float*)d_in[3];
    const float* Wl   = (const float*)d_in[4];
    const float* bl   = (const float*)d_in[5];
    const float* Wr   = (const float*)d_in[6];
    const float* br   = (const float*)d_in[7];
    const float* att  = (const float*)d_in[8];
    const float* bias = (const float*)d_in[9];
    float* out = (float*)d_out;

    static cudaStream_t s_csr = nullptr;
    static cudaEvent_t  ev_fork = nullptr, ev_join = nullptr;
    if (!s_csr) {
        cudaStreamCreateWithFlags(&s_csr, cudaStreamNonBlocking);
        cudaEventCreateWithFlags(&ev_fork, cudaEventDisableTiming);
        cudaEventCreateWithFlags(&ev_join, cudaEventDisableTiming);
    }

    // fork: padded-CSR build on side stream
    cudaEventRecord(ev_fork, 0);
    cudaStreamWaitEvent(s_csr, ev_fork, 0);
    zero_kernel<<<(N_NODES + 255) / 256, 256, 0, s_csr>>>();
    fill_kernel<<<(E_EDGES + 255) / 256, 256, 0, s_csr>>>(ei);
    cudaEventRecord(ev_join, s_csr);

    // main stream: W fragment split + LN + mma GEMM
    prep_b_kernel<<<32, 256>>>(Wl, Wr);
    ln_gemm_kernel<<<NTILES, 512>>>(x, lng, lnb, bl, br);

    // join, then aggregate
    cudaStreamWaitEvent(0, ev_join, 0);
    agg_kernel<<<(N_NODES + 7) / 8, 256>>>(x, att, bias, out);
}

// round 15
// speedup vs baseline: 1.1839x; 1.0836x over previous
#include <cuda_runtime.h>
#include <cuda_bf16.h>
#include <cuda_fp16.h>
#include <cstdint>

#define N_NODES 50000
#define E_EDGES 800000
#define DIM 128
#define GROWS 64
#define NTILES ((N_NODES + GROWS - 1) / GROWS)
#define LDA 136        // padded A row length (bf16) -> conflict-free ldmatrix
#define CAP 128        // padded-CSR capacity per destination

// ---------------- device scratch (no allocations allowed) ----------------
__device__ __half g_xl[(size_t)N_NODES * DIM];
__device__ float  g_xr[(size_t)N_NODES * DIM];
__device__ int    g_cnt[N_NODES];
__device__ int    g_srcp[(size_t)N_NODES * CAP];
// B fragments merged: [ks][ng][lane] -> uint4 {hi.k01, hi.k89, lo.k01, lo.k89}
__device__ __align__(16) uint4 g_Bf[8192];

// ---------------- padded-CSR build ----------------
__global__ void zero_kernel() {
    int i = blockIdx.x * blockDim.x + threadIdx.x;
    if (i < N_NODES) g_cnt[i] = 0;
}
__global__ void fill_kernel(const int* __restrict__ ei) {
    int e = blockIdx.x * blockDim.x + threadIdx.x;
    if (e < E_EDGES) {
        int s = ei[e];
        int d = ei[E_EDGES + e];
        int p = atomicAdd(&g_cnt[d], 1);
        if (p < CAP) g_srcp[(size_t)d * CAP + p] = s;
    }
}

// ---------------- one-time W split into merged B fragments ----------------
__device__ __forceinline__ uint32_t pack_bf16(float a, float b) {
    __nv_bfloat16 ba = __float2bfloat16(a), bb = __float2bfloat16(b);
    return (uint32_t)__bfloat16_as_ushort(bb) << 16 | __bfloat16_as_ushort(ba);
}
__global__ void prep_b_kernel(const float* __restrict__ Wl, const float* __restrict__ Wr) {
    int i = blockIdx.x * blockDim.x + threadIdx.x;   // 0..8191
    if (i >= 8192) return;
    const int lane = i & 31;
    const int ng   = (i >> 5) & 31;
    const int ks   = i >> 10;
    const int n    = ng * 8 + (lane >> 2);
    const int k0   = ks * 16 + (lane & 3) * 2;
    const float* W = (n < 128) ? Wl : Wr;
    const int nn   = n & 127;
    const float v0 = W[(k0    ) * 128 + nn];
    const float v1 = W[(k0 + 1) * 128 + nn];
    const float v8 = W[(k0 + 8) * 128 + nn];
    const float v9 = W[(k0 + 9) * 128 + nn];
    float h0 = __bfloat162float(__float2bfloat16(v0));
    float h1 = __bfloat162float(__float2bfloat16(v1));
    float h8 = __bfloat162float(__float2bfloat16(v8));
    float h9 = __bfloat162float(__float2bfloat16(v9));
    g_Bf[i] = make_uint4(pack_bf16(h0, h1), pack_bf16(h8, h9),
                         pack_bf16(v0 - h0, v1 - h1), pack_bf16(v8 - h8, v9 - h9));
}

// ---------------- mma helpers ----------------
__device__ __forceinline__ uint32_t smem_u32(const void* p) {
    uint32_t a;
    asm("{ .reg .u64 t; cvta.to.shared.u64 t, %1; cvt.u32.u64 %0, t; }" : "=r"(a) : "l"(p));
    return a;
}
__device__ __forceinline__ void ldsm_x4(uint32_t* r, uint32_t addr) {
    asm volatile("ldmatrix.sync.aligned.m8n8.x4.shared.b16 {%0,%1,%2,%3}, [%4];"
                 : "=r"(r[0]), "=r"(r[1]), "=r"(r[2]), "=r"(r[3]) : "r"(addr));
}
__device__ __forceinline__ void mma_bf16(float* d, const uint32_t* a, uint32_t b0, uint32_t b1) {
    asm volatile(
        "mma.sync.aligned.m16n8k16.row.col.f32.bf16.bf16.f32 "
        "{%0,%1,%2,%3}, {%4,%5,%6,%7}, {%8,%9}, {%0,%1,%2,%3};"
        : "+f"(d[0]), "+f"(d[1]), "+f"(d[2]), "+f"(d[3])
        : "r"(a[0]), "r"(a[1]), "r"(a[2]), "r"(a[3]), "r"(b0), "r"(b1));
}

#define SM_BYTES 18432

// ---------------- LayerNorm + dual GEMM (tile 64 x 256, 2-pass split) ----------------
__global__ __launch_bounds__(512, 2)
void ln_gemm_kernel(const float* __restrict__ x,
                    const float* __restrict__ ln_g, const float* __restrict__ ln_b,
                    const float* __restrict__ bl, const float* __restrict__ br)
{
    __shared__ __align__(16) char smem[SM_BYTES];
    const uint32_t sb = smem_u32(smem);
    const int tid  = threadIdx.x;
    const int wid  = tid >> 5;
    const int lane = tid & 31;
    const int base = blockIdx.x * GROWS;

    // LayerNorm -> bf16 A image (16 warps x 4 rows)
    {
        const float4 gv = reinterpret_cast<const float4*>(ln_g)[lane];
        const float4 bv = reinterpret_cast<const float4*>(ln_b)[lane];
        #pragma unroll
        for (int i = 0; i < 4; i++) {
            const int nl = i * 16 + wid;
            const int n  = base + nl;
            float4 v = make_float4(0.f, 0.f, 0.f, 0.f);
            if (n < N_NODES)
                v = reinterpret_cast<const float4*>(x + (size_t)n * DIM)[lane];
            float s = v.x + v.y + v.z + v.w;
            #pragma unroll
            for (int w = 16; w; w >>= 1) s += __shfl_xor_sync(0xffffffffu, s, w);
            const float mu = s * (1.0f / 128.0f);
            const float dx = v.x - mu, dy = v.y - mu, dz = v.z - mu, dw = v.w - mu;
            float q = dx * dx + dy * dy + dz * dz + dw * dw;
            #pragma unroll
            for (int w = 16; w; w >>= 1) q += __shfl_xor_sync(0xffffffffu, q, w);
            const float rs = rsqrtf(q * (1.0f / 128.0f) + 1e-5f);
            const uint32_t off = (uint32_t)(nl * LDA + lane * 4) * 2;
            *reinterpret_cast<uint2*>(smem + off) = make_uint2(
                pack_bf16(dx * rs * gv.x + bv.x, dy * rs * gv.y + bv.y),
                pack_bf16(dz * rs * gv.z + bv.z, dw * rs * gv.w + bv.w));
        }
    }
    __syncthreads();

    // ---- MMA mainloop: warp tile 32x32, 2 passes, merged B fragments ----
    const int wm = wid & 1;
    const int wn = wid >> 1;

    const uint32_t aRow = (uint32_t)(wm * 32 + (lane & 15));
    const uint32_t aK   = (uint32_t)((lane >> 4) * 8);
    const uint32_t aHi  = sb + (aRow * LDA + aK) * 2;

    float d[2][4][4];
    #pragma unroll
    for (int mf = 0; mf < 2; mf++)
        #pragma unroll
        for (int nf = 0; nf < 4; nf++)
            #pragma unroll
            for (int j = 0; j < 4; j++) d[mf][nf][j] = 0.f;

    #pragma unroll 1
    for (int ks = 0; ks < 8; ks++) {
        const uint32_t kb = (uint32_t)ks * 32;
        uint32_t ah[2][4];
        ldsm_x4(ah[0], aHi + kb);
        ldsm_x4(ah[1], aHi + 16 * LDA * 2 + kb);
        const int fbase = (ks * 32 + wn * 4) * 32 + lane;
        uint4 bf[4];
        #pragma unroll
        for (int nf = 0; nf < 4; nf++) bf[nf] = g_Bf[fbase + nf * 32];
        #pragma unroll
        for (int nf = 0; nf < 4; nf++)
            #pragma unroll
            for (int mf = 0; mf < 2; mf++) {
                mma_bf16(d[mf][nf], ah[mf], bf[nf].x, bf[nf].y);
                mma_bf16(d[mf][nf], ah[mf], bf[nf].z, bf[nf].w);
            }
    }

    // ---- Epilogue: smem-staged, coalesced stores ----
    const int half  = wn >> 2;
    const int cbase = (wn & 3) * 32;
    __syncthreads();

    // Phase A: xl (fp16)
    if (half == 0) {
        #pragma unroll
        for (int mf = 0; mf < 2; mf++) {
            const int r0 = wm * 32 + mf * 16 + (lane >> 2);
            #pragma unroll
            for (int nf = 0; nf < 4; nf++) {
                const int c = cbase + nf * 8 + (lane & 3) * 2;
                const float2 bv = *reinterpret_cast<const float2*>(&bl[c]);
                *reinterpret_cast<__half2*>(smem + (r0 * 136 + c) * 2) =
                    __floats2half2_rn(d[mf][nf][0] + bv.x, d[mf][nf][1] + bv.y);
                *reinterpret_cast<__half2*>(smem + ((r0 + 8) * 136 + c) * 2) =
                    __floats2half2_rn(d[mf][nf][2] + bv.x, d[mf][nf][3] + bv.y);
            }
        }
    }
    __syncthreads();
    #pragma unroll
    for (int i = tid; i < 1024; i += 512) {
        const int row = i >> 4, c16 = i & 15;
        const int n = base + row;
        if (n < N_NODES)
            *reinterpret_cast<uint4*>(reinterpret_cast<char*>(g_xl) + ((size_t)n * DIM + c16 * 8) * 2) =
                *reinterpret_cast<const uint4*>(smem + row * 272 + c16 * 16);
    }

    // Phases B/C: xr (fp32) in two 64-col half-tiles
    #pragma unroll 1
    for (int ph = 0; ph < 2; ph++) {
        __syncthreads();
        if (half == 1 && ((wn >> 1) & 1) == ph) {
            const int cl0 = (wn & 1) * 32;
            #pragma unroll
            for (int mf = 0; mf < 2; mf++) {
                const int r0 = wm * 32 + mf * 16 + (lane >> 2);
                #pragma unroll
                for (int nf = 0; nf < 4; nf++) {
                    const int cl = cl0 + nf * 8 + (lane & 3) * 2;
                    const float2 bv = *reinterpret_cast<const float2*>(&br[ph * 64 + cl]);
                    *reinterpret_cast<float2*>(smem + (r0 * 72 + cl) * 4) =
                        make_float2(d[mf][nf][0] + bv.x, d[mf][nf][1] + bv.y);
                    *reinterpret_cast<float2*>(smem + ((r0 + 8) * 72 + cl) * 4) =
                        make_float2(d[mf][nf][2] + bv.x, d[mf][nf][3] + bv.y);
                }
            }
        }
        __syncthreads();
        #pragma unroll
        for (int i = tid; i < 1024; i += 512) {
            const int row = i >> 4, c16 = i & 15;
            const int n = base + row;
            if (n < N_NODES)
                *reinterpret_cast<uint4*>(g_xr + (size_t)n * DIM + ph * 64 + c16 * 4) =
                    *reinterpret_cast<const uint4*>(smem + row * 288 + c16 * 16);
        }
    }
}

// ---------------- warp-per-destination aggregation (register-lean, 2-edge groups) ----------------
// R12 structure; 2-edge unroll + launch_bounds(256,5) to lift occupancy
// (62 regs / 32 warps -> <=51 regs / 40 warps per SM).
__global__ __launch_bounds__(256, 5)
void agg_kernel(const float* __restrict__ x, const float* __restrict__ att,
                const float* __restrict__ bias, float* __restrict__ out)
{
    const int warp = threadIdx.x >> 5;
    const int lane = threadIdx.x & 31;
    const int nid  = blockIdx.x * 8 + warp;
    if (nid >= N_NODES) return;

    const int deg = min(g_cnt[nid], CAP);
    const size_t st = (size_t)nid * CAP;

    const float4 xr4 = *reinterpret_cast<const float4*>(g_xr + (size_t)nid * DIM + lane * 4);
    const float4 a4  = reinterpret_cast<const float4*>(att)[lane];
    const float4 aP  = make_float4(0.575f * a4.x, 0.575f * a4.y, 0.575f * a4.z, 0.575f * a4.w);
    const float4 aQ  = make_float4(0.425f * a4.x, 0.425f * a4.y, 0.425f * a4.z, 0.425f * a4.w);

    float  dsum = 0.f;
    float4 acc  = make_float4(0.f, 0.f, 0.f, 0.f);

    const __half* xlp = g_xl;

    for (int b = 0; b < deg; b += 32) {
        const int cnt = min(32, deg - b);
        const int my_src = (lane < cnt) ? g_srcp[st + b + lane] : 0;

        int e = 0;
        for (; e + 2 <= cnt; e += 2) {
            const int s0 = __shfl_sync(0xffffffffu, my_src, e);
            const int s1 = __shfl_sync(0xffffffffu, my_src, e + 1);
            const uint2 u0 = *reinterpret_cast<const uint2*>(xlp + (size_t)s0 * DIM + lane * 4);
            const uint2 u1 = *reinterpret_cast<const uint2*>(xlp + (size_t)s1 * DIM + lane * 4);

            const float2 f0a = __half22float2(*reinterpret_cast<const __half2*>(&u0.x));
            const float2 f0b = __half22float2(*reinterpret_cast<const __half2*>(&u0.y));
            const float2 f1a = __half22float2(*reinterpret_cast<const __half2*>(&u1.x));
            const float2 f1b = __half22float2(*reinterpret_cast<const __half2*>(&u1.y));

            float p0, p1, z;
            z = f0a.x + xr4.x; p0  = aP.x * z + aQ.x * fabsf(z);
            z = f0a.y + xr4.y; p0 += aP.y * z + aQ.y * fabsf(z);
            z = f0b.x + xr4.z; p0 += aP.z * z + aQ.z * fabsf(z);
            z = f0b.y + xr4.w; p0 += aP.w * z + aQ.w * fabsf(z);
            z = f1a.x + xr4.x; p1  = aP.x * z + aQ.x * fabsf(z);
            z = f1a.y + xr4.y; p1 += aP.y * z + aQ.y * fabsf(z);
            z = f1b.x + xr4.z; p1 += aP.z * z + aQ.z * fabsf(z);
            z = f1b.y + xr4.w; p1 += aP.w * z + aQ.w * fabsf(z);

            p0 += __shfl_xor_sync(0xffffffffu, p0, 1);
            p1 += __shfl_xor_sync(0xffffffffu, p1, 1);
            p0 += __shfl_xor_sync(0xffffffffu, p0, 2);
            p1 += __shfl_xor_sync(0xffffffffu, p1, 2);

            const float w0 = __expf(p0);
            const float w1 = __expf(p1);
            dsum += w0 + w1;
            acc.x = fmaf(f1a.x, w1, fmaf(f0a.x, w0, acc.x));
            acc.y = fmaf(f1a.y, w1, fmaf(f0a.y, w0, acc.y));
            acc.z = fmaf(f1b.x, w1, fmaf(f0b.x, w0, acc.z));
            acc.w = fmaf(f1b.y, w1, fmaf(f0b.y, w0, acc.w));
        }
        if (e < cnt) {
            const int s0 = __shfl_sync(0xffffffffu, my_src, e);
            const uint2 u0 = *reinterpret_cast<const uint2*>(xlp + (size_t)s0 * DIM + lane * 4);
            const float2 f0a = __half22float2(*reinterpret_cast<const __half2*>(&u0.x));
            const float2 f0b = __half22float2(*reinterpret_cast<const __half2*>(&u0.y));
            float p0, z;
            z = f0a.x + xr4.x; p0  = aP.x * z + aQ.x * fabsf(z);
            z = f0a.y + xr4.y; p0 += aP.y * z + aQ.y * fabsf(z);
            z = f0b.x + xr4.z; p0 += aP.z * z + aQ.z * fabsf(z);
            z = f0b.y + xr4.w; p0 += aP.w * z + aQ.w * fabsf(z);
            p0 += __shfl_xor_sync(0xffffffffu, p0, 1);
            p0 += __shfl_xor_sync(0xffffffffu, p0, 2);
            const float w0 = __expf(p0);
            dsum += w0;
            acc.x = fmaf(f0a.x, w0, acc.x);
            acc.y = fmaf(f0a.y, w0, acc.y);
            acc.z = fmaf(f0b.x, w0, acc.z);
            acc.w = fmaf(f0b.y, w0, acc.w);
        }
    }

    const float inv = 1.0f / (dsum + 1e-16f);
    const float4 bias4 = reinterpret_cast<const float4*>(bias)[lane];
    const float4 x4 = *reinterpret_cast<const float4*>(x + (size_t)nid * DIM + lane * 4);
    float4 o;
    o.x = x4.x + fmaxf(fmaf(acc.x, inv, bias4.x), 0.f);
    o.y = x4.y + fmaxf(fmaf(acc.y, inv, bias4.y), 0.f);
    o.z = x4.z + fmaxf(fmaf(acc.z, inv, bias4.z), 0.f);
    o.w = x4.w + fmaxf(fmaf(acc.w, inv, bias4.w), 0.f);
    *reinterpret_cast<float4*>(out + (size_t)nid * DIM + lane * 4) = o;
}

// ---------------- launch ----------------
extern "C" void kernel_launch(void* const* d_in, const int* in_sizes, int n_in,
                              void* d_out, int out_size)
{
    const float* x    = (const float*)d_in[0];
    const int*   ei   = (const int*)d_in[1];
    const float* lng  = (const float*)d_in[2];
    const float* lnb  = (const float*)d_in[3];
    const float* Wl   = (const float*)d_in[4];
    const float* bl   = (const float*)d_in[5];
    const float* Wr   = (const float*)d_in[6];
    const float* br   = (const float*)d_in[7];
    const float* att  = (const float*)d_in[8];
    const float* bias = (const float*)d_in[9];
    float* out = (float*)d_out;

    static cudaStream_t s_csr = nullptr;
    static cudaEvent_t  ev_fork = nullptr, ev_join = nullptr;
    if (!s_csr) {
        cudaStreamCreateWithFlags(&s_csr, cudaStreamNonBlocking);
        cudaEventCreateWithFlags(&ev_fork, cudaEventDisableTiming);
        cudaEventCreateWithFlags(&ev_join, cudaEventDisableTiming);
    }

    // fork: padded-CSR build on side stream
    cudaEventRecord(ev_fork, 0);
    cudaStreamWaitEvent(s_csr, ev_fork, 0);
    zero_kernel<<<(N_NODES + 255) / 256, 256, 0, s_csr>>>();
    fill_kernel<<<(E_EDGES + 255) / 256, 256, 0, s_csr>>>(ei);
    cudaEventRecord(ev_join, s_csr);

    // main stream: W fragment split + LN + mma GEMM
    prep_b_kernel<<<32, 256>>>(Wl, Wr);
    ln_gemm_kernel<<<NTILES, 512>>>(x, lng, lnb, bl, br);

    // join, then aggregate
    cudaStreamWaitEvent(0, ev_join, 0);
    agg_kernel<<<(N_NODES + 7) / 8, 256>>>(x, att, bias, out);
}

// round 16
// speedup vs baseline: 1.2016x; 1.0150x over previous
#include <cuda_runtime.h>
#include <cuda_bf16.h>
#include <cuda_fp16.h>
#include <cstdint>

#define N_NODES 50000
#define E_EDGES 800000
#define DIM 128
#define GROWS 64
#define NTILES ((N_NODES + GROWS - 1) / GROWS)
#define LDA 136        // padded A row length (bf16) -> conflict-free ldmatrix
#define CAP 128        // padded-CSR capacity per destination
#define CHUNK 16       // edges staged per cp.async batch (4 KB/warp)

// ---------------- device scratch (no allocations allowed) ----------------
__device__ __half g_xl[(size_t)N_NODES * DIM];
__device__ float  g_xr[(size_t)N_NODES * DIM];
__device__ int    g_cnt[N_NODES];
__device__ int    g_srcp[(size_t)N_NODES * CAP];
// B fragments merged: [ks][ng][lane] -> uint4 {hi.k01, hi.k89, lo.k01, lo.k89}
__device__ __align__(16) uint4 g_Bf[8192];

// ---------------- padded-CSR build ----------------
__global__ void zero_kernel() {
    int i = blockIdx.x * blockDim.x + threadIdx.x;
    if (i < N_NODES) g_cnt[i] = 0;
}
__global__ void fill_kernel(const int* __restrict__ ei) {
    int e = blockIdx.x * blockDim.x + threadIdx.x;
    if (e < E_EDGES) {
        int s = ei[e];
        int d = ei[E_EDGES + e];
        int p = atomicAdd(&g_cnt[d], 1);
        if (p < CAP) g_srcp[(size_t)d * CAP + p] = s;
    }
}

// ---------------- one-time W split into merged B fragments ----------------
__device__ __forceinline__ uint32_t pack_bf16(float a, float b) {
    __nv_bfloat16 ba = __float2bfloat16(a), bb = __float2bfloat16(b);
    return (uint32_t)__bfloat16_as_ushort(bb) << 16 | __bfloat16_as_ushort(ba);
}
__global__ void prep_b_kernel(const float* __restrict__ Wl, const float* __restrict__ Wr) {
    int i = blockIdx.x * blockDim.x + threadIdx.x;   // 0..8191
    if (i >= 8192) return;
    const int lane = i & 31;
    const int ng   = (i >> 5) & 31;
    const int ks   = i >> 10;
    const int n    = ng * 8 + (lane >> 2);
    const int k0   = ks * 16 + (lane & 3) * 2;
    const float* W = (n < 128) ? Wl : Wr;
    const int nn   = n & 127;
    const float v0 = W[(k0    ) * 128 + nn];
    const float v1 = W[(k0 + 1) * 128 + nn];
    const float v8 = W[(k0 + 8) * 128 + nn];
    const float v9 = W[(k0 + 9) * 128 + nn];
    float h0 = __bfloat162float(__float2bfloat16(v0));
    float h1 = __bfloat162float(__float2bfloat16(v1));
    float h8 = __bfloat162float(__float2bfloat16(v8));
    float h9 = __bfloat162float(__float2bfloat16(v9));
    g_Bf[i] = make_uint4(pack_bf16(h0, h1), pack_bf16(h8, h9),
                         pack_bf16(v0 - h0, v1 - h1), pack_bf16(v8 - h8, v9 - h9));
}

// ---------------- helpers ----------------
__device__ __forceinline__ uint32_t smem_u32(const void* p) {
    uint32_t a;
    asm("{ .reg .u64 t; cvta.to.shared.u64 t, %1; cvt.u32.u64 %0, t; }" : "=r"(a) : "l"(p));
    return a;
}
__device__ __forceinline__ void ldsm_x4(uint32_t* r, uint32_t addr) {
    asm volatile("ldmatrix.sync.aligned.m8n8.x4.shared.b16 {%0,%1,%2,%3}, [%4];"
                 : "=r"(r[0]), "=r"(r[1]), "=r"(r[2]), "=r"(r[3]) : "r"(addr));
}
__device__ __forceinline__ void mma_bf16(float* d, const uint32_t* a, uint32_t b0, uint32_t b1) {
    asm volatile(
        "mma.sync.aligned.m16n8k16.row.col.f32.bf16.bf16.f32 "
        "{%0,%1,%2,%3}, {%4,%5,%6,%7}, {%8,%9}, {%0,%1,%2,%3};"
        : "+f"(d[0]), "+f"(d[1]), "+f"(d[2]), "+f"(d[3])
        : "r"(a[0]), "r"(a[1]), "r"(a[2]), "r"(a[3]), "r"(b0), "r"(b1));
}

#define SM_BYTES 18432

// ---------------- LayerNorm + dual GEMM (tile 64 x 256, 2-pass split) ----------------
__global__ __launch_bounds__(512, 2)
void ln_gemm_kernel(const float* __restrict__ x,
                    const float* __restrict__ ln_g, const float* __restrict__ ln_b,
                    const float* __restrict__ bl, const float* __restrict__ br)
{
    __shared__ __align__(16) char smem[SM_BYTES];
    const uint32_t sb = smem_u32(smem);
    const int tid  = threadIdx.x;
    const int wid  = tid >> 5;
    const int lane = tid & 31;
    const int base = blockIdx.x * GROWS;

    // LayerNorm -> bf16 A image (16 warps x 4 rows)
    {
        const float4 gv = reinterpret_cast<const float4*>(ln_g)[lane];
        const float4 bv = reinterpret_cast<const float4*>(ln_b)[lane];
        #pragma unroll
        for (int i = 0; i < 4; i++) {
            const int nl = i * 16 + wid;
            const int n  = base + nl;
            float4 v = make_float4(0.f, 0.f, 0.f, 0.f);
            if (n < N_NODES)
                v = reinterpret_cast<const float4*>(x + (size_t)n * DIM)[lane];
            float s = v.x + v.y + v.z + v.w;
            #pragma unroll
            for (int w = 16; w; w >>= 1) s += __shfl_xor_sync(0xffffffffu, s, w);
            const float mu = s * (1.0f / 128.0f);
            const float dx = v.x - mu, dy = v.y - mu, dz = v.z - mu, dw = v.w - mu;
            float q = dx * dx + dy * dy + dz * dz + dw * dw;
            #pragma unroll
            for (int w = 16; w; w >>= 1) q += __shfl_xor_sync(0xffffffffu, q, w);
            const float rs = rsqrtf(q * (1.0f / 128.0f) + 1e-5f);
            const uint32_t off = (uint32_t)(nl * LDA + lane * 4) * 2;
            *reinterpret_cast<uint2*>(smem + off) = make_uint2(
                pack_bf16(dx * rs * gv.x + bv.x, dy * rs * gv.y + bv.y),
                pack_bf16(dz * rs * gv.z + bv.z, dw * rs * gv.w + bv.w));
        }
    }
    __syncthreads();

    // ---- MMA mainloop: warp tile 32x32, 2 passes, merged B fragments ----
    const int wm = wid & 1;
    const int wn = wid >> 1;

    const uint32_t aRow = (uint32_t)(wm * 32 + (lane & 15));
    const uint32_t aK   = (uint32_t)((lane >> 4) * 8);
    const uint32_t aHi  = sb + (aRow * LDA + aK) * 2;

    float d[2][4][4];
    #pragma unroll
    for (int mf = 0; mf < 2; mf++)
        #pragma unroll
        for (int nf = 0; nf < 4; nf++)
            #pragma unroll
            for (int j = 0; j < 4; j++) d[mf][nf][j] = 0.f;

    #pragma unroll 1
    for (int ks = 0; ks < 8; ks++) {
        const uint32_t kb = (uint32_t)ks * 32;
        uint32_t ah[2][4];
        ldsm_x4(ah[0], aHi + kb);
        ldsm_x4(ah[1], aHi + 16 * LDA * 2 + kb);
        const int fbase = (ks * 32 + wn * 4) * 32 + lane;
        uint4 bf[4];
        #pragma unroll
        for (int nf = 0; nf < 4; nf++) bf[nf] = g_Bf[fbase + nf * 32];
        #pragma unroll
        for (int nf = 0; nf < 4; nf++)
            #pragma unroll
            for (int mf = 0; mf < 2; mf++) {
                mma_bf16(d[mf][nf], ah[mf], bf[nf].x, bf[nf].y);
                mma_bf16(d[mf][nf], ah[mf], bf[nf].z, bf[nf].w);
            }
    }

    // ---- Epilogue: smem-staged, coalesced stores ----
    const int half  = wn >> 2;
    const int cbase = (wn & 3) * 32;
    __syncthreads();

    // Phase A: xl (fp16)
    if (half == 0) {
        #pragma unroll
        for (int mf = 0; mf < 2; mf++) {
            const int r0 = wm * 32 + mf * 16 + (lane >> 2);
            #pragma unroll
            for (int nf = 0; nf < 4; nf++) {
                const int c = cbase + nf * 8 + (lane & 3) * 2;
                const float2 bv = *reinterpret_cast<const float2*>(&bl[c]);
                *reinterpret_cast<__half2*>(smem + (r0 * 136 + c) * 2) =
                    __floats2half2_rn(d[mf][nf][0] + bv.x, d[mf][nf][1] + bv.y);
                *reinterpret_cast<__half2*>(smem + ((r0 + 8) * 136 + c) * 2) =
                    __floats2half2_rn(d[mf][nf][2] + bv.x, d[mf][nf][3] + bv.y);
            }
        }
    }
    __syncthreads();
    #pragma unroll
    for (int i = tid; i < 1024; i += 512) {
        const int row = i >> 4, c16 = i & 15;
        const int n = base + row;
        if (n < N_NODES)
            *reinterpret_cast<uint4*>(reinterpret_cast<char*>(g_xl) + ((size_t)n * DIM + c16 * 8) * 2) =
                *reinterpret_cast<const uint4*>(smem + row * 272 + c16 * 16);
    }

    // Phases B/C: xr (fp32) in two 64-col half-tiles
    #pragma unroll 1
    for (int ph = 0; ph < 2; ph++) {
        __syncthreads();
        if (half == 1 && ((wn >> 1) & 1) == ph) {
            const int cl0 = (wn & 1) * 32;
            #pragma unroll
            for (int mf = 0; mf < 2; mf++) {
                const int r0 = wm * 32 + mf * 16 + (lane >> 2);
                #pragma unroll
                for (int nf = 0; nf < 4; nf++) {
                    const int cl = cl0 + nf * 8 + (lane & 3) * 2;
                    const float2 bv = *reinterpret_cast<const float2*>(&br[ph * 64 + cl]);
                    *reinterpret_cast<float2*>(smem + (r0 * 72 + cl) * 4) =
                        make_float2(d[mf][nf][0] + bv.x, d[mf][nf][1] + bv.y);
                    *reinterpret_cast<float2*>(smem + ((r0 + 8) * 72 + cl) * 4) =
                        make_float2(d[mf][nf][2] + bv.x, d[mf][nf][3] + bv.y);
                }
            }
        }
        __syncthreads();
        #pragma unroll
        for (int i = tid; i < 1024; i += 512) {
            const int row = i >> 4, c16 = i & 15;
            const int n = base + row;
            if (n < N_NODES)
                *reinterpret_cast<uint4*>(g_xr + (size_t)n * DIM + ph * 64 + c16 * 4) =
                    *reinterpret_cast<const uint4*>(smem + row * 288 + c16 * 16);
        }
    }
}

// ---------------- warp-per-destination aggregation, cp.async staged gather ----------------
// One warp per node. Per 16-edge chunk: issue ALL scattered 8B copies via
// cp.async (16 outstanding, zero register cost), wait once, compute from smem.
// Each lane reads only the bytes it copied -> per-thread wait_group suffices.
__global__ __launch_bounds__(256)
void agg_kernel(const float* __restrict__ x, const float* __restrict__ att,
                const float* __restrict__ bias, float* __restrict__ out)
{
    __shared__ __align__(16) __half s_buf[8][CHUNK][DIM];   // 32 KB

    const int warp = threadIdx.x >> 5;
    const int lane = threadIdx.x & 31;
    const int nid  = blockIdx.x * 8 + warp;
    if (nid >= N_NODES) return;

    const int deg = min(g_cnt[nid], CAP);
    const size_t st = (size_t)nid * CAP;

    const float4 xr4 = *reinterpret_cast<const float4*>(g_xr + (size_t)nid * DIM + lane * 4);
    const float4 a4  = reinterpret_cast<const float4*>(att)[lane];
    const float4 aP  = make_float4(0.575f * a4.x, 0.575f * a4.y, 0.575f * a4.z, 0.575f * a4.w);
    const float4 aQ  = make_float4(0.425f * a4.x, 0.425f * a4.y, 0.425f * a4.z, 0.425f * a4.w);

    float  dsum = 0.f;
    float4 acc  = make_float4(0.f, 0.f, 0.f, 0.f);

    const __half* xlp = g_xl;
    const uint32_t sbuf = smem_u32(&s_buf[warp][0][0]) + (uint32_t)lane * 8;

    for (int b = 0; b < deg; b += CHUNK) {
        const int cnt = min(CHUNK, deg - b);
        const int my_src = (lane < cnt) ? g_srcp[st + b + lane] : 0;

        // Issue phase: cnt scattered 8B copies, all outstanding
        for (int e = 0; e < cnt; e++) {
            const int s = __shfl_sync(0xffffffffu, my_src, e);
            const __half* gp = xlp + (size_t)s * DIM + lane * 4;
            asm volatile("cp.async.ca.shared.global [%0], [%1], 8;\n"
                         :: "r"(sbuf + (uint32_t)e * 256), "l"(gp));
        }
        asm volatile("cp.async.commit_group;\n");
        asm volatile("cp.async.wait_group 0;\n" ::: "memory");

        // Compute phase from smem (2-edge groups)
        int e = 0;
        for (; e + 2 <= cnt; e += 2) {
            uint2 u0, u1;
            asm volatile("ld.shared.v2.u32 {%0,%1}, [%2];"
                         : "=r"(u0.x), "=r"(u0.y) : "r"(sbuf + (uint32_t)e * 256));
            asm volatile("ld.shared.v2.u32 {%0,%1}, [%2];"
                         : "=r"(u1.x), "=r"(u1.y) : "r"(sbuf + (uint32_t)(e + 1) * 256));

            const float2 f0a = __half22float2(*reinterpret_cast<const __half2*>(&u0.x));
            const float2 f0b = __half22float2(*reinterpret_cast<const __half2*>(&u0.y));
            const float2 f1a = __half22float2(*reinterpret_cast<const __half2*>(&u1.x));
            const float2 f1b = __half22float2(*reinterpret_cast<const __half2*>(&u1.y));

            float p0, p1, z;
            z = f0a.x + xr4.x; p0  = aP.x * z + aQ.x * fabsf(z);
            z = f0a.y + xr4.y; p0 += aP.y * z + aQ.y * fabsf(z);
            z = f0b.x + xr4.z; p0 += aP.z * z + aQ.z * fabsf(z);
            z = f0b.y + xr4.w; p0 += aP.w * z + aQ.w * fabsf(z);
            z = f1a.x + xr4.x; p1  = aP.x * z + aQ.x * fabsf(z);
            z = f1a.y + xr4.y; p1 += aP.y * z + aQ.y * fabsf(z);
            z = f1b.x + xr4.z; p1 += aP.z * z + aQ.z * fabsf(z);
            z = f1b.y + xr4.w; p1 += aP.w * z + aQ.w * fabsf(z);

            p0 += __shfl_xor_sync(0xffffffffu, p0, 1);
            p1 += __shfl_xor_sync(0xffffffffu, p1, 1);
            p0 += __shfl_xor_sync(0xffffffffu, p0, 2);
            p1 += __shfl_xor_sync(0xffffffffu, p1, 2);

            const float w0 = __expf(p0);
            const float w1 = __expf(p1);
            dsum += w0 + w1;
            acc.x = fmaf(f1a.x, w1, fmaf(f0a.x, w0, acc.x));
            acc.y = fmaf(f1a.y, w1, fmaf(f0a.y, w0, acc.y));
            acc.z = fmaf(f1b.x, w1, fmaf(f0b.x, w0, acc.z));
            acc.w = fmaf(f1b.y, w1, fmaf(f0b.y, w0, acc.w));
        }
        if (e < cnt) {
            uint2 u0;
            asm volatile("ld.shared.v2.u32 {%0,%1}, [%2];"
                         : "=r"(u0.x), "=r"(u0.y) : "r"(sbuf + (uint32_t)e * 256));
            const float2 f0a = __half22float2(*reinterpret_cast<const __half2*>(&u0.x));
            const float2 f0b = __half22float2(*reinterpret_cast<const __half2*>(&u0.y));
            float p0, z;
            z = f0a.x + xr4.x; p0  = aP.x * z + aQ.x * fabsf(z);
            z = f0a.y + xr4.y; p0 += aP.y * z + aQ.y * fabsf(z);
            z = f0b.x + xr4.z; p0 += aP.z * z + aQ.z * fabsf(z);
            z = f0b.y + xr4.w; p0 += aP.w * z + aQ.w * fabsf(z);
            p0 += __shfl_xor_sync(0xffffffffu, p0, 1);
            p0 += __shfl_xor_sync(0xffffffffu, p0, 2);
            const float w0 = __expf(p0);
            dsum += w0;
            acc.x = fmaf(f0a.x, w0, acc.x);
            acc.y = fmaf(f0a.y, w0, acc.y);
            acc.z = fmaf(f0b.x, w0, acc.z);
            acc.w = fmaf(f0b.y, w0, acc.w);
        }
        __syncwarp();
    }

    const float inv = 1.0f / (dsum + 1e-16f);
    const float4 bias4 = reinterpret_cast<const float4*>(bias)[lane];
    const float4 x4 = *reinterpret_cast<const float4*>(x + (size_t)nid * DIM + lane * 4);
    float4 o;
    o.x = x4.x + fmaxf(fmaf(acc.x, inv, bias4.x), 0.f);
    o.y = x4.y + fmaxf(fmaf(acc.y, inv, bias4.y), 0.f);
    o.z = x4.z + fmaxf(fmaf(acc.z, inv, bias4.z), 0.f);
    o.w = x4.w + fmaxf(fmaf(acc.w, inv, bias4.w), 0.f);
    *reinterpret_cast<float4*>(out + (size_t)nid * DIM + lane * 4) = o;
}

// ---------------- launch ----------------
extern "C" void kernel_launch(void* const* d_in, const int* in_sizes, int n_in,
                              void* d_out, int out_size)
{
    const float* x    = (const float*)d_in[0];
    const int*   ei   = (const int*)d_in[1];
    const float* lng  = (const float*)d_in[2];
    const float* lnb  = (const float*)d_in[3];
    const float* Wl   = (const float*)d_in[4];
    const float* bl   = (const float*)d_in[5];
    const float* Wr   = (const float*)d_in[6];
    const float* br   = (const float*)d_in[7];
    const float* att  = (const float*)d_in[8];
    const float* bias = (const float*)d_in[9];
    float* out = (float*)d_out;

    static cudaStream_t s_csr = nullptr;
    static cudaEvent_t  ev_fork = nullptr, ev_join = nullptr;
    if (!s_csr) {
        cudaStreamCreateWithFlags(&s_csr, cudaStreamNonBlocking);
        cudaEventCreateWithFlags(&ev_fork, cudaEventDisableTiming);
        cudaEventCreateWithFlags(&ev_join, cudaEventDisableTiming);
    }

    // fork: padded-CSR build on side stream
    cudaEventRecord(ev_fork, 0);
    cudaStreamWaitEvent(s_csr, ev_fork, 0);
    zero_kernel<<<(N_NODES + 255) / 256, 256, 0, s_csr>>>();
    fill_kernel<<<(E_EDGES + 255) / 256, 256, 0, s_csr>>>(ei);
    cudaEventRecord(ev_join, s_csr);

    // main stream: W fragment split + LN + mma GEMM
    prep_b_kernel<<<32, 256>>>(Wl, Wr);
    ln_gemm_kernel<<<NTILES, 512>>>(x, lng, lnb, bl, br);

    // join, then aggregate
    cudaStreamWaitEvent(0, ev_join, 0);
    agg_kernel<<<(N_NODES + 7) / 8, 256>>>(x, att, bias, out);
}